// round 7
// baseline (speedup 1.0000x reference)
#include <cuda_runtime.h>
#include <cuda.h>
#include <cuda_fp16.h>
#include <cstdint>
#include <cstdio>

// ============================================================================
// Problem dims
// ============================================================================
#define M_DIM 8192
#define N_DIM 4096
#define K_DIM 4096
#define LORA_R 8
#define SCALE_F 2.0f

// Persistent tiling: tile 256(M) x 128(N), BK=64, 1024 tiles
#define TM 256
#define TN 128
#define BK 64
#define STAGES 4
#define KTILES (K_DIM / BK)
#define NTILES ((M_DIM / TM) * (N_DIM / TN))   // 32*32 = 1024
#define NT_CNT (N_DIM / TN)                    // 32

// Scratch + sync state (device globals: no runtime allocation)
__device__ __half g_xh[(size_t)M_DIM * K_DIM];   // x in fp16, row-major [M, K]
__device__ __half g_wh[(size_t)N_DIM * K_DIM];   // W' = base + 2*(B@A) fp16, [N, K]
__device__ unsigned g_cta_epoch[1024];           // per-CTA launch counter (epoch)
__device__ unsigned g_wdone[32];                 // W chunk ready counters (monotonic)
__device__ unsigned g_xdone[64];                 // x chunk ready counters (monotonic)

// ============================================================================
// Common helpers
// ============================================================================
__device__ __forceinline__ uint32_t smem_u32(const void* p) {
    uint32_t a;
    asm("{ .reg .u64 t; cvta.to.shared.u64 t, %1; cvt.u32.u64 %0, t; }"
        : "=r"(a) : "l"(p));
    return a;
}

__device__ __forceinline__ void wait_cnt(const unsigned* p, unsigned thresh) {
    unsigned v;
    while (true) {
        asm volatile("ld.global.acquire.gpu.u32 %0, [%1];" : "=r"(v) : "l"(p));
        if ((int)(v - thresh) >= 0) break;
        asm volatile("nanosleep.u32 128;");
    }
}

// ---------------- sm_103a-only helpers -------------------------------------
#define MBARRIER_INIT(addr, count) \
    asm volatile("mbarrier.init.shared.b64 [%0], %1;" :: "r"((uint32_t)(addr)), "r"((uint32_t)(count)) : "memory")

#define MBARRIER_EXPECT_TX(addr, bytes) \
    asm volatile("mbarrier.arrive.expect_tx.shared.b64 _, [%0], %1;" :: "r"((uint32_t)(addr)), "r"((uint32_t)(bytes)) : "memory")

#define MBARRIER_ARRIVE(addr) \
    asm volatile("mbarrier.arrive.shared.b64 _, [%0];" :: "r"((uint32_t)(addr)) : "memory")

#define MBARRIER_WAIT_PARITY(mbar_addr, phase_parity) do { \
    uint32_t _mbar = (uint32_t)(mbar_addr); \
    uint32_t _parity = (uint32_t)(phase_parity); \
    uint32_t _done; \
    asm volatile( \
        "{\n\t.reg .pred p;\n\t" \
        "mbarrier.try_wait.parity.acquire.cta.shared::cta.b64 p, [%1], %2;\n\t" \
        "selp.b32 %0, 1, 0, p;\n\t}" \
        : "=r"(_done) : "r"(_mbar), "r"(_parity) : "memory"); \
    if (!_done) { \
        asm volatile( \
            "{\n\t.reg .pred P1;\n\t" \
            "WAIT_LOOP_%=:\n\t" \
            "mbarrier.try_wait.parity.acquire.cta.shared::cta.b64 P1, [%0], %1, 0x989680;\n\t" \
            "@P1 bra.uni WAIT_DONE_%=;\n\t" \
            "bra.uni WAIT_LOOP_%=;\n\t" \
            "WAIT_DONE_%=:\n\t}" \
            :: "r"(_mbar), "r"(_parity) : "memory"); \
    } \
} while (0)

#define TCGEN05_ALLOC(smem_addr, nCols) \
    asm volatile("tcgen05.alloc.cta_group::1.sync.aligned.shared::cta.b32 [%0], %1;" \
                 :: "r"((uint32_t)(smem_addr)), "r"((uint32_t)(nCols)) : "memory")

#define TCGEN05_DEALLOC(tmem_addr, nCols) \
    asm volatile("tcgen05.dealloc.cta_group::1.sync.aligned.b32 %0, %1;" \
                 :: "r"(tmem_addr), "r"((uint32_t)(nCols)))

#define TCGEN05_RELINQUISH() \
    asm volatile("tcgen05.relinquish_alloc_permit.cta_group::1.sync.aligned;")

#define TCGEN05_COMMIT(mbar_addr) \
    asm volatile("tcgen05.commit.cta_group::1.mbarrier::arrive::one.shared::cluster.b64 [%0];" \
                 :: "r"((uint32_t)(mbar_addr)) : "memory")

#define TCGEN05_FENCE_AFTER()  asm volatile("tcgen05.fence::after_thread_sync;" ::: "memory")
#define TCGEN05_FENCE_BEFORE() asm volatile("tcgen05.fence::before_thread_sync;" ::: "memory")
#define TCGEN05_WAIT_LD()      asm volatile("tcgen05.wait::ld.sync.aligned;" ::: "memory")

#define TCGEN05_LD_32X32B_X32(r, tmem_addr) \
    asm volatile( \
        "tcgen05.ld.sync.aligned.32x32b.x32.b32 " \
        "{%0, %1, %2, %3, %4, %5, %6, %7, " \
        " %8, %9, %10, %11, %12, %13, %14, %15, " \
        " %16, %17, %18, %19, %20, %21, %22, %23, " \
        " %24, %25, %26, %27, %28, %29, %30, %31}, [%32];" \
        : "=r"((r)[0]),  "=r"((r)[1]),  "=r"((r)[2]),  "=r"((r)[3]), \
          "=r"((r)[4]),  "=r"((r)[5]),  "=r"((r)[6]),  "=r"((r)[7]), \
          "=r"((r)[8]),  "=r"((r)[9]),  "=r"((r)[10]), "=r"((r)[11]), \
          "=r"((r)[12]), "=r"((r)[13]), "=r"((r)[14]), "=r"((r)[15]), \
          "=r"((r)[16]), "=r"((r)[17]), "=r"((r)[18]), "=r"((r)[19]), \
          "=r"((r)[20]), "=r"((r)[21]), "=r"((r)[22]), "=r"((r)[23]), \
          "=r"((r)[24]), "=r"((r)[25]), "=r"((r)[26]), "=r"((r)[27]), \
          "=r"((r)[28]), "=r"((r)[29]), "=r"((r)[30]), "=r"((r)[31]) \
        : "r"(tmem_addr))

// K-major SW128 SMEM descriptor (LBO=1, SBO=64, version=1, layout=SW128)
static constexpr uint64_t SMEM_DESC_BASE_SW128 =
    (uint64_t(2) << 61) | (uint64_t(1) << 46) | (uint64_t(64) << 32) | (uint64_t(1) << 16);

#define MAKE_SMEM_DESC(base_addr) \
    (SMEM_DESC_BASE_SW128 | ((uint64_t)((base_addr) >> 4) & 0x3FFF))

#define TMA_LOAD_2D(dst, map, cx, cy, mbar) \
    asm volatile( \
        "cp.async.bulk.tensor.2d.shared::cta.global.tile.mbarrier::complete_tx::bytes " \
        "[%0], [%1, {%2, %3}], [%4];" \
        :: "r"((uint32_t)(dst)), "l"(map), "r"((int)(cx)), "r"((int)(cy)), "r"((uint32_t)(mbar)) : "memory")

// ============================================================================
// In-kernel conversion slices (chunk = 128 rows x 4096 cols = 131072 float4)
// ============================================================================
static constexpr int CH4 = 128 * (K_DIM / 4);   // 131072 float4 per chunk

__device__ __forceinline__ void conv_x_slice(int c, int gw, int nslices, int lane,
                                             const float4* __restrict__ x4) {
    int q = (CH4 + nslices - 1) / nslices;
    int lo = gw * q;
    int hi = lo + q; if (hi > CH4) hi = CH4;
    uint2* dst = reinterpret_cast<uint2*>(g_xh);
    size_t cb = (size_t)c * CH4;
    for (int i = lo + lane; i < hi; i += 32) {
        float4 v = x4[cb + i];
        __half2 h0 = __floats2half2_rn(v.x, v.y);
        __half2 h1 = __floats2half2_rn(v.z, v.w);
        uint2 u;
        u.x = *reinterpret_cast<uint32_t*>(&h0);
        u.y = *reinterpret_cast<uint32_t*>(&h1);
        dst[cb + i] = u;
    }
}

__device__ __forceinline__ void conv_w_slice(int c, int gw, int nslices, int lane,
                                             const float4* __restrict__ base4,
                                             const float4* __restrict__ A4,
                                             const float* __restrict__ Bm) {
    int q = (CH4 + nslices - 1) / nslices;
    int lo = gw * q;
    int hi = lo + q; if (hi > CH4) hi = CH4;
    uint2* dst = reinterpret_cast<uint2*>(g_wh);
    size_t cb = (size_t)c * CH4;
    for (int i = lo + lane; i < hi; i += 32) {
        int o  = (c << 7) + (i >> 10);      // row within W
        int kq = i & 1023;
        float4 acc = base4[cb + i];
#pragma unroll
        for (int r = 0; r < LORA_R; r++) {
            float b = SCALE_F * __ldg(&Bm[o * LORA_R + r]);
            float4 a = __ldg(&A4[r * (K_DIM / 4) + kq]);
            acc.x = fmaf(b, a.x, acc.x);
            acc.y = fmaf(b, a.y, acc.y);
            acc.z = fmaf(b, a.z, acc.z);
            acc.w = fmaf(b, a.w, acc.w);
        }
        __half2 h0 = __floats2half2_rn(acc.x, acc.y);
        __half2 h1 = __floats2half2_rn(acc.z, acc.w);
        uint2 u;
        u.x = *reinterpret_cast<uint32_t*>(&h0);
        u.y = *reinterpret_cast<uint32_t*>(&h1);
        dst[cb + i] = u;
    }
}

// ============================================================================
// Fused persistent kernel: convert (overlapped) + GEMM + bias
// ============================================================================
static constexpr int A_HALF    = 128 * BK * 2;            // 16384
static constexpr int A_BYTES   = 2 * A_HALF;              // 32768
static constexpr int B_BYTES   = TN * BK * 2;             // 16384
static constexpr int STG_BYTES = A_BYTES + B_BYTES;       // 49152
static constexpr int SMEM_TMEMPTR = 0;
static constexpr int BAR_FULL  = 16;
static constexpr int BAR_EMPTY = 48;
static constexpr int BAR_DONE  = 80;
static constexpr int BAR_EPI   = 96;
static constexpr int SMEM_TILES = 1024;
static constexpr int GEMM_SMEM = SMEM_TILES + STAGES * STG_BYTES;  // 197632

static constexpr uint32_t GEMM_IDESC_N128 =
    (1u << 4) | ((128 / 8) << 17) | ((128 / 16) << 24);

// ---- fallback constants ----
static constexpr int FB_ROWB   = 144;
static constexpr int FB_A_TILE = 256 * FB_ROWB;
static constexpr int FB_B_TILE = 128 * FB_ROWB;
static constexpr int FB_STAGE  = FB_A_TILE + FB_B_TILE;

#if !defined(__CUDA_ARCH__) || !defined(__CUDA_ARCH_FEAT_SM103_ALL)
__device__ __forceinline__ void cp_async16(uint32_t dst, const void* src) {
    asm volatile("cp.async.cg.shared.global [%0], [%1], 16;" :: "r"(dst), "l"(src) : "memory");
}
__device__ __forceinline__ void ldsm_x4(uint32_t* r, uint32_t addr) {
    asm volatile("ldmatrix.sync.aligned.m8n8.x4.shared.b16 {%0,%1,%2,%3}, [%4];"
                 : "=r"(r[0]), "=r"(r[1]), "=r"(r[2]), "=r"(r[3]) : "r"(addr));
}
__device__ __forceinline__ void mma16816(float* c, const uint32_t* a, uint32_t b0, uint32_t b1) {
    asm volatile("mma.sync.aligned.m16n8k16.row.col.f32.f16.f16.f32 "
                 "{%0,%1,%2,%3}, {%4,%5,%6,%7}, {%8,%9}, {%0,%1,%2,%3};"
                 : "+f"(c[0]), "+f"(c[1]), "+f"(c[2]), "+f"(c[3])
                 : "r"(a[0]), "r"(a[1]), "r"(a[2]), "r"(a[3]), "r"(b0), "r"(b1));
}
#endif

__global__ void __launch_bounds__(256, 1) lora_gemm_kernel(
    const __grid_constant__ CUtensorMap tmap_a,
    const __grid_constant__ CUtensorMap tmap_b,
    const float4* __restrict__ x4,
    const float4* __restrict__ base4,
    const float4* __restrict__ A4,
    const float* __restrict__ Bm,
    const float* __restrict__ bias,
    float* __restrict__ out)
{
    extern __shared__ __align__(1024) char smem[];
    __shared__ unsigned s_epoch;
    const uint32_t sb = smem_u32(smem);
    const int tid = threadIdx.x;
    const int wid = tid >> 5;
    const int lane = tid & 31;

    if (tid == 0) s_epoch = atomicAdd(&g_cta_epoch[blockIdx.x], 1u);

#if defined(__CUDA_ARCH_FEAT_SM103_ALL)
    // ============ persistent tcgen05 + overlapped conversion ================
    if (wid == 4) {
        TCGEN05_ALLOC(sb + SMEM_TMEMPTR, 512);
        TCGEN05_RELINQUISH();
    }
    if (tid == 0) {
#pragma unroll
        for (int s = 0; s < STAGES; s++) {
            MBARRIER_INIT(sb + BAR_FULL + 8 * s, 1);
            MBARRIER_INIT(sb + BAR_EMPTY + 8 * s, 1);
        }
#pragma unroll
        for (int b = 0; b < 2; b++) {
            MBARRIER_INIT(sb + BAR_DONE + 8 * b, 1);
            MBARRIER_INIT(sb + BAR_EPI + 8 * b, 1);
        }
    }
    __syncthreads();
    TCGEN05_FENCE_AFTER();

    const unsigned epoch = s_epoch;
    const unsigned te = epoch + 1u;

    uint32_t tmem;
    asm volatile("ld.shared.b32 %0, [%1];" : "=r"(tmem) : "r"(sb + SMEM_TMEMPTR));

    // ---- conversion duty: warps 0-3 and 6-7 ----
    if (wid < 4 || wid >= 6) {
        const int wslot6 = (wid < 4) ? wid : (wid - 2);   // 0..5
        const int g6 = blockIdx.x * 6 + wslot6;
        const int n6 = gridDim.x * 6;
        for (int c = 0; c < 32; c++) {
            conv_w_slice(c, g6, n6, lane, base4, A4, Bm);
            __threadfence();
            if (lane == 0) atomicAdd(&g_wdone[c], 1u);
        }
        if (wid < 4) {
            const int g4 = blockIdx.x * 4 + wid;
            const int n4 = gridDim.x * 4;
            for (int c = 0; c < 8; c++) {
                conv_x_slice(c, g4, n4, lane, x4);
                __threadfence();
                if (lane == 0) atomicAdd(&g_xdone[c], 1u);
            }
        } else {
            const int g2 = blockIdx.x * 2 + (wid - 6);
            const int n2 = gridDim.x * 2;
            for (int c = 8; c < 64; c++) {
                conv_x_slice(c, g2, n2, lane, x4);
                __threadfence();
                if (lane == 0) atomicAdd(&g_xdone[c], 1u);
            }
        }
    }

    if (wid == 5) {
        // ---- TMA producer warp (gated on chunk-ready counters) ----
        uint32_t elected;
        asm volatile("{\n\t.reg .pred P;\n\telect.sync _|P, 0xFFFFFFFF;\n\tselp.b32 %0, 1, 0, P;\n\t}"
                     : "=r"(elected));
        const unsigned w_t = 6u * gridDim.x * te;
        int s = 0, ph = 1;
        for (int t = blockIdx.x; t < NTILES; t += gridDim.x) {
            const int m0 = (t / NT_CNT) * TM;
            const int n0 = (t % NT_CNT) * TN;
            const int cm = m0 >> 7;
            wait_cnt(&g_xdone[cm],     ((cm < 8)     ? 4u : 2u) * gridDim.x * te);
            wait_cnt(&g_xdone[cm + 1], ((cm + 1 < 8) ? 4u : 2u) * gridDim.x * te);
            wait_cnt(&g_wdone[n0 >> 7], w_t);
            asm volatile("fence.proxy.async;" ::: "memory");
            for (int kt = 0; kt < KTILES; kt++) {
                MBARRIER_WAIT_PARITY(sb + BAR_EMPTY + 8 * s, ph);
                if (elected) {
                    uint32_t full = sb + BAR_FULL + 8 * s;
                    MBARRIER_EXPECT_TX(full, STG_BYTES);
                    uint32_t dst = sb + SMEM_TILES + s * STG_BYTES;
                    TMA_LOAD_2D(dst,           &tmap_a, kt * BK, m0,       full);
                    TMA_LOAD_2D(dst + A_HALF,  &tmap_a, kt * BK, m0 + 128, full);
                    TMA_LOAD_2D(dst + A_BYTES, &tmap_b, kt * BK, n0,       full);
                }
                if (++s == STAGES) { s = 0; ph ^= 1; }
            }
        }
    } else if (wid == 4) {
        // ---- MMA warp ----
        uint32_t elected;
        asm volatile("{\n\t.reg .pred P;\n\telect.sync _|P, 0xFFFFFFFF;\n\tselp.b32 %0, 1, 0, P;\n\t}"
                     : "=r"(elected));
        int s = 0, ph = 0;
        int i = 0;
        for (int t = blockIdx.x; t < NTILES; t += gridDim.x, i++) {
            const int b = i & 1;
            const uint32_t dbase = tmem + b * 256;
            if (i >= 2) {
                MBARRIER_WAIT_PARITY(sb + BAR_EPI + 8 * b, ((i >> 1) ^ 1) & 1);
            }
            for (int kt = 0; kt < KTILES; kt++) {
                MBARRIER_WAIT_PARITY(sb + BAR_FULL + 8 * s, ph);
                if (elected) {
                    uint32_t stg = sb + SMEM_TILES + s * STG_BYTES;
                    uint64_t ad0 = MAKE_SMEM_DESC(stg);
                    uint64_t ad1 = MAKE_SMEM_DESC(stg + A_HALF);
                    uint64_t bd  = MAKE_SMEM_DESC(stg + A_BYTES);
                    uint32_t en0 = (kt == 0) ? 0u : 1u;
#pragma unroll
                    for (int j = 0; j < BK / 16; j++) {
                        uint32_t en = (j == 0) ? en0 : 1u;
                        uint32_t zero = 0u;
#define MMA_ONE(doff, adesc) \
                        asm volatile( \
                            "{\n\t.reg .pred p;\n\tsetp.ne.u32 p, %5, 0;\n\t" \
                            "tcgen05.mma.cta_group::1.kind::f16 [%0], %1, %2, %3, {%4, %4, %4, %4}, p;\n\t}" \
                            :: "r"(dbase + (doff)), "l"(adesc), "l"(bd + j * 2), \
                               "r"(GEMM_IDESC_N128), "r"(zero), "r"(en) : "memory")
                        MMA_ONE(0,   ad0 + j * 2);
                        MMA_ONE(128, ad1 + j * 2);
#undef MMA_ONE
                    }
                    TCGEN05_COMMIT(sb + BAR_EMPTY + 8 * s);
                }
                if (++s == STAGES) { s = 0; ph ^= 1; }
            }
            if (elected) {
                TCGEN05_COMMIT(sb + BAR_DONE + 8 * b);
            }
        }
    } else if (wid < 4) {
        // ---- epilogue warpgroup (after its conversion duty) ----
        int i = 0;
        for (int t = blockIdx.x; t < NTILES; t += gridDim.x, i++) {
            const int b = i & 1;
            const int m0 = (t / NT_CNT) * TM;
            const int n0 = (t % NT_CNT) * TN;
            const uint32_t dbase = tmem + b * 256;
            MBARRIER_WAIT_PARITY(sb + BAR_DONE + 8 * b, (i >> 1) & 1);
            TCGEN05_FENCE_AFTER();
#pragma unroll
            for (int mh = 0; mh < 2; mh++) {
                const int row_g = m0 + mh * 128 + wid * 32 + lane;
                float* orow = out + (size_t)row_g * N_DIM + n0;
#pragma unroll
                for (int cb = 0; cb < TN / 32; cb++) {
                    uint32_t r[32];
                    TCGEN05_LD_32X32B_X32(r, dbase + mh * 128 + cb * 32);
                    TCGEN05_WAIT_LD();
#pragma unroll
                    for (int c4 = 0; c4 < 8; c4++) {
                        int col = cb * 32 + c4 * 4;
                        float4 v;
                        v.x = __uint_as_float(r[c4 * 4 + 0]) + __ldg(&bias[n0 + col + 0]);
                        v.y = __uint_as_float(r[c4 * 4 + 1]) + __ldg(&bias[n0 + col + 1]);
                        v.z = __uint_as_float(r[c4 * 4 + 2]) + __ldg(&bias[n0 + col + 2]);
                        v.w = __uint_as_float(r[c4 * 4 + 3]) + __ldg(&bias[n0 + col + 3]);
                        *reinterpret_cast<float4*>(orow + col) = v;
                    }
                }
            }
            TCGEN05_FENCE_BEFORE();
            asm volatile("bar.sync 1, 128;" ::: "memory");
            if (tid == 0) {
                MBARRIER_ARRIVE(sb + BAR_EPI + 8 * b);
            }
        }
    }

    __syncthreads();
    if (wid == 4) {
        TCGEN05_DEALLOC(tmem, 512);
    }

#else
    // ======================= mma.sync fallback path ==========================
    (void)tmap_a; (void)tmap_b;
    __syncthreads();
    const unsigned epoch = s_epoch;
    const unsigned te = epoch + 1u;

    // conversion phase: all 8 warps slice all chunks
    {
        const int g8 = blockIdx.x * 8 + wid;
        const int n8 = gridDim.x * 8;
        for (int c = 0; c < 32; c++) {
            conv_w_slice(c, g8, n8, lane, base4, A4, Bm);
            __threadfence();
            if (lane == 0) atomicAdd(&g_wdone[c], 1u);
        }
        for (int c = 0; c < 64; c++) {
            conv_x_slice(c, g8, n8, lane, x4);
            __threadfence();
            if (lane == 0) atomicAdd(&g_xdone[c], 1u);
        }
    }
    if (tid == 0) {
        for (int c = 0; c < 32; c++) wait_cnt(&g_wdone[c], 8u * gridDim.x * te);
        for (int c = 0; c < 64; c++) wait_cnt(&g_xdone[c], 8u * gridDim.x * te);
    }
    __syncthreads();

    const __half* xh = g_xh;
    const __half* wh = g_wh;
    const int wm = (wid >> 1) * 64;
    const int wn = (wid & 1) * 64;
    const int l = lane;
    const int a_r = (l & 7) + ((l >> 3) & 1) * 8;
    const int a_c = (l >> 4) * 8;
    const int b_r = (l & 7) + ((l >> 4) & 1) * 8;
    const int b_c = ((l >> 3) & 1) * 8;

    for (int t = blockIdx.x; t < NTILES; t += gridDim.x) {
        const int m0 = (t / NT_CNT) * TM;
        const int n0 = (t % NT_CNT) * TN;
        float acc[4][8][4];
#pragma unroll
        for (int mt = 0; mt < 4; mt++)
#pragma unroll
            for (int nt = 0; nt < 8; nt++)
#pragma unroll
                for (int q = 0; q < 4; q++) acc[mt][nt][q] = 0.0f;

        {
            const __half* ga = xh + (size_t)(m0 + tid) * K_DIM;
            uint32_t da = sb + tid * FB_ROWB;
#pragma unroll
            for (int q = 0; q < 8; q++) cp_async16(da + q * 16, ga + q * 8);
            int brow = tid >> 1, half = tid & 1;
            const __half* gb = wh + (size_t)(n0 + brow) * K_DIM + half * 32;
            uint32_t db = sb + FB_A_TILE + brow * FB_ROWB + half * 64;
#pragma unroll
            for (int q = 0; q < 4; q++) cp_async16(db + q * 16, gb + q * 8);
            asm volatile("cp.async.commit_group;" ::: "memory");
        }

        for (int kt = 0; kt < KTILES; kt++) {
            if (kt + 1 < KTILES) {
                int s = (kt + 1) & 1;
                const __half* ga = xh + (size_t)(m0 + tid) * K_DIM + (kt + 1) * BK;
                uint32_t da = sb + s * FB_STAGE + tid * FB_ROWB;
#pragma unroll
                for (int q = 0; q < 8; q++) cp_async16(da + q * 16, ga + q * 8);
                int brow = tid >> 1, half = tid & 1;
                const __half* gb = wh + (size_t)(n0 + brow) * K_DIM + (kt + 1) * BK + half * 32;
                uint32_t db = sb + s * FB_STAGE + FB_A_TILE + brow * FB_ROWB + half * 64;
#pragma unroll
                for (int q = 0; q < 4; q++) cp_async16(db + q * 16, gb + q * 8);
                asm volatile("cp.async.commit_group;" ::: "memory");
                asm volatile("cp.async.wait_group 1;" ::: "memory");
            } else {
                asm volatile("cp.async.wait_group 0;" ::: "memory");
            }
            __syncthreads();

            uint32_t sA = sb + (kt & 1) * FB_STAGE;
            uint32_t sB = sA + FB_A_TILE;
#pragma unroll
            for (int ks = 0; ks < BK / 16; ks++) {
                uint32_t afrag[4][4];
#pragma unroll
                for (int mt = 0; mt < 4; mt++) {
                    uint32_t addr = sA + (wm + mt * 16 + a_r) * FB_ROWB + (ks * 16 + a_c) * 2;
                    ldsm_x4(afrag[mt], addr);
                }
                uint32_t bfrag[4][4];
#pragma unroll
                for (int p = 0; p < 4; p++) {
                    uint32_t addr = sB + (wn + p * 16 + b_r) * FB_ROWB + (ks * 16 + b_c) * 2;
                    ldsm_x4(bfrag[p], addr);
                }
#pragma unroll
                for (int mt = 0; mt < 4; mt++)
#pragma unroll
                    for (int nt = 0; nt < 8; nt++)
                        mma16816(acc[mt][nt], afrag[mt],
                                 bfrag[nt >> 1][(nt & 1) * 2], bfrag[nt >> 1][(nt & 1) * 2 + 1]);
            }
            __syncthreads();
        }

#pragma unroll
        for (int mt = 0; mt < 4; mt++) {
#pragma unroll
            for (int nt = 0; nt < 8; nt++) {
                int r0 = m0 + wm + mt * 16 + (l >> 2);
                int c0 = n0 + wn + nt * 8 + (l & 3) * 2;
                float bx = __ldg(&bias[c0]);
                float by = __ldg(&bias[c0 + 1]);
                float2 v0 = make_float2(acc[mt][nt][0] + bx, acc[mt][nt][1] + by);
                float2 v1 = make_float2(acc[mt][nt][2] + bx, acc[mt][nt][3] + by);
                *reinterpret_cast<float2*>(&out[(size_t)r0 * N_DIM + c0]) = v0;
                *reinterpret_cast<float2*>(&out[(size_t)(r0 + 8) * N_DIM + c0]) = v1;
            }
        }
        __syncthreads();
    }
#endif
}

// ============================================================================
// Host launch
// ============================================================================
typedef CUresult (*tmap_encode_t)(CUtensorMap*, CUtensorMapDataType, cuuint32_t, void*,
                                  const cuuint64_t*, const cuuint64_t*, const cuuint32_t*,
                                  const cuuint32_t*, CUtensorMapInterleave, CUtensorMapSwizzle,
                                  CUtensorMapL2promotion, CUtensorMapFloatOOBfill);

extern "C" void kernel_launch(void* const* d_in, const int* in_sizes, int n_in,
                              void* d_out, int out_size) {
    (void)in_sizes; (void)n_in; (void)out_size;
    const float* x    = (const float*)d_in[0];
    const float* base = (const float*)d_in[1];
    const float* lA   = (const float*)d_in[2];
    const float* lB   = (const float*)d_in[3];
    const float* bias = (const float*)d_in[4];
    float* out = (float*)d_out;

    void* xh_p = nullptr;
    void* wh_p = nullptr;
    cudaGetSymbolAddress(&xh_p, g_xh);
    cudaGetSymbolAddress(&wh_p, g_wh);

    static tmap_encode_t encode = nullptr;
    if (!encode) {
        void* pfn = nullptr;
        cudaDriverEntryPointQueryResult qres;
#if CUDART_VERSION >= 12050
        cudaGetDriverEntryPointByVersion("cuTensorMapEncodeTiled", &pfn, 12000,
                                         cudaEnableDefault, &qres);
#else
        cudaGetDriverEntryPoint("cuTensorMapEncodeTiled", &pfn, cudaEnableDefault, &qres);
#endif
        encode = (tmap_encode_t)pfn;
    }

    CUtensorMap mapA{}, mapB{};
    if (encode) {
        {
            cuuint64_t dims[2]    = {K_DIM, M_DIM};
            cuuint64_t strides[1] = {K_DIM * sizeof(__half)};
            cuuint32_t box[2]     = {BK, 128};
            cuuint32_t es[2]      = {1, 1};
            encode(&mapA, CU_TENSOR_MAP_DATA_TYPE_FLOAT16, 2, xh_p, dims, strides, box, es,
                   CU_TENSOR_MAP_INTERLEAVE_NONE, CU_TENSOR_MAP_SWIZZLE_128B,
                   CU_TENSOR_MAP_L2_PROMOTION_L2_128B, CU_TENSOR_MAP_FLOAT_OOB_FILL_NONE);
        }
        {
            cuuint64_t dims[2]    = {K_DIM, N_DIM};
            cuuint64_t strides[1] = {K_DIM * sizeof(__half)};
            cuuint32_t box[2]     = {BK, TN};
            cuuint32_t es[2]      = {1, 1};
            encode(&mapB, CU_TENSOR_MAP_DATA_TYPE_FLOAT16, 2, wh_p, dims, strides, box, es,
                   CU_TENSOR_MAP_INTERLEAVE_NONE, CU_TENSOR_MAP_SWIZZLE_128B,
                   CU_TENSOR_MAP_L2_PROMOTION_L2_128B, CU_TENSOR_MAP_FLOAT_OOB_FILL_NONE);
        }
    }

    int dev = 0, smcount = 148;
    cudaGetDevice(&dev);
    cudaDeviceGetAttribute(&smcount, cudaDevAttrMultiProcessorCount, dev);
    if (smcount < 1) smcount = 148;
    if (smcount > 1024) smcount = 1024;

    cudaFuncSetAttribute(lora_gemm_kernel, cudaFuncAttributeMaxDynamicSharedMemorySize,
                         GEMM_SMEM);
    lora_gemm_kernel<<<smcount, 256, GEMM_SMEM>>>(
        mapA, mapB,
        (const float4*)x, (const float4*)base, (const float4*)lA, lB,
        bias, out);
}

// round 8
// speedup vs baseline: 1.6624x; 1.6624x over previous
#include <cuda_runtime.h>
#include <cuda.h>
#include <cuda_fp16.h>
#include <cstdint>
#include <cstdio>

// ============================================================================
// Problem dims
// ============================================================================
#define M_DIM 8192
#define N_DIM 4096
#define K_DIM 4096
#define LORA_R 8
#define SCALE_F 2.0f

// Persistent tiling: tile 256(M) x 128(N), BK=64, 1024 tiles
#define TM 256
#define TN 128
#define BK 64
#define STAGES 4
#define KTILES (K_DIM / BK)
#define NTILES ((M_DIM / TM) * (N_DIM / TN))   // 32*32 = 1024
#define NT_CNT (N_DIM / TN)                    // 32
#define XCHUNK_BLOCKS 16                       // converter blocks per x chunk

// Scratch + sync state (device globals: no runtime allocation)
__device__ __half g_xh[(size_t)M_DIM * K_DIM];   // x in fp16, row-major [M, K]
__device__ __half g_wh[(size_t)N_DIM * K_DIM];   // W' = base + 2*(B@A) fp16, [N, K]
__device__ unsigned g_cta_epoch[1024];           // per-CTA launch counter (epoch)
__device__ unsigned g_xdone[64];                 // x chunk ready counters (monotonic)

// ============================================================================
// Common helpers
// ============================================================================
__device__ __forceinline__ uint32_t smem_u32(const void* p) {
    uint32_t a;
    asm("{ .reg .u64 t; cvta.to.shared.u64 t, %1; cvt.u32.u64 %0, t; }"
        : "=r"(a) : "l"(p));
    return a;
}

__device__ __forceinline__ void wait_cnt(const unsigned* p, unsigned thresh) {
    unsigned v;
    while (true) {
        asm volatile("ld.global.acquire.gpu.u32 %0, [%1];" : "=r"(v) : "l"(p));
        if ((int)(v - thresh) >= 0) break;
        asm volatile("nanosleep.u32 256;");
    }
}

// ---------------- sm_103a-only helpers -------------------------------------
#define MBARRIER_INIT(addr, count) \
    asm volatile("mbarrier.init.shared.b64 [%0], %1;" :: "r"((uint32_t)(addr)), "r"((uint32_t)(count)) : "memory")

#define MBARRIER_EXPECT_TX(addr, bytes) \
    asm volatile("mbarrier.arrive.expect_tx.shared.b64 _, [%0], %1;" :: "r"((uint32_t)(addr)), "r"((uint32_t)(bytes)) : "memory")

#define MBARRIER_ARRIVE(addr) \
    asm volatile("mbarrier.arrive.shared.b64 _, [%0];" :: "r"((uint32_t)(addr)) : "memory")

#define MBARRIER_WAIT_PARITY(mbar_addr, phase_parity) do { \
    uint32_t _mbar = (uint32_t)(mbar_addr); \
    uint32_t _parity = (uint32_t)(phase_parity); \
    uint32_t _done; \
    asm volatile( \
        "{\n\t.reg .pred p;\n\t" \
        "mbarrier.try_wait.parity.acquire.cta.shared::cta.b64 p, [%1], %2;\n\t" \
        "selp.b32 %0, 1, 0, p;\n\t}" \
        : "=r"(_done) : "r"(_mbar), "r"(_parity) : "memory"); \
    if (!_done) { \
        asm volatile( \
            "{\n\t.reg .pred P1;\n\t" \
            "WAIT_LOOP_%=:\n\t" \
            "mbarrier.try_wait.parity.acquire.cta.shared::cta.b64 P1, [%0], %1, 0x989680;\n\t" \
            "@P1 bra.uni WAIT_DONE_%=;\n\t" \
            "bra.uni WAIT_LOOP_%=;\n\t" \
            "WAIT_DONE_%=:\n\t}" \
            :: "r"(_mbar), "r"(_parity) : "memory"); \
    } \
} while (0)

#define TCGEN05_ALLOC(smem_addr, nCols) \
    asm volatile("tcgen05.alloc.cta_group::1.sync.aligned.shared::cta.b32 [%0], %1;" \
                 :: "r"((uint32_t)(smem_addr)), "r"((uint32_t)(nCols)) : "memory")

#define TCGEN05_DEALLOC(tmem_addr, nCols) \
    asm volatile("tcgen05.dealloc.cta_group::1.sync.aligned.b32 %0, %1;" \
                 :: "r"(tmem_addr), "r"((uint32_t)(nCols)))

#define TCGEN05_RELINQUISH() \
    asm volatile("tcgen05.relinquish_alloc_permit.cta_group::1.sync.aligned;")

#define TCGEN05_COMMIT(mbar_addr) \
    asm volatile("tcgen05.commit.cta_group::1.mbarrier::arrive::one.shared::cluster.b64 [%0];" \
                 :: "r"((uint32_t)(mbar_addr)) : "memory")

#define TCGEN05_FENCE_AFTER()  asm volatile("tcgen05.fence::after_thread_sync;" ::: "memory")
#define TCGEN05_FENCE_BEFORE() asm volatile("tcgen05.fence::before_thread_sync;" ::: "memory")
#define TCGEN05_WAIT_LD()      asm volatile("tcgen05.wait::ld.sync.aligned;" ::: "memory")

#define TCGEN05_LD_32X32B_X32(r, tmem_addr) \
    asm volatile( \
        "tcgen05.ld.sync.aligned.32x32b.x32.b32 " \
        "{%0, %1, %2, %3, %4, %5, %6, %7, " \
        " %8, %9, %10, %11, %12, %13, %14, %15, " \
        " %16, %17, %18, %19, %20, %21, %22, %23, " \
        " %24, %25, %26, %27, %28, %29, %30, %31}, [%32];" \
        : "=r"((r)[0]),  "=r"((r)[1]),  "=r"((r)[2]),  "=r"((r)[3]), \
          "=r"((r)[4]),  "=r"((r)[5]),  "=r"((r)[6]),  "=r"((r)[7]), \
          "=r"((r)[8]),  "=r"((r)[9]),  "=r"((r)[10]), "=r"((r)[11]), \
          "=r"((r)[12]), "=r"((r)[13]), "=r"((r)[14]), "=r"((r)[15]), \
          "=r"((r)[16]), "=r"((r)[17]), "=r"((r)[18]), "=r"((r)[19]), \
          "=r"((r)[20]), "=r"((r)[21]), "=r"((r)[22]), "=r"((r)[23]), \
          "=r"((r)[24]), "=r"((r)[25]), "=r"((r)[26]), "=r"((r)[27]), \
          "=r"((r)[28]), "=r"((r)[29]), "=r"((r)[30]), "=r"((r)[31]) \
        : "r"(tmem_addr))

// K-major SW128 SMEM descriptor (LBO=1, SBO=64, version=1, layout=SW128)
static constexpr uint64_t SMEM_DESC_BASE_SW128 =
    (uint64_t(2) << 61) | (uint64_t(1) << 46) | (uint64_t(64) << 32) | (uint64_t(1) << 16);

#define MAKE_SMEM_DESC(base_addr) \
    (SMEM_DESC_BASE_SW128 | ((uint64_t)((base_addr) >> 4) & 0x3FFF))

#define TMA_LOAD_2D(dst, map, cx, cy, mbar) \
    asm volatile( \
        "cp.async.bulk.tensor.2d.shared::cta.global.tile.mbarrier::complete_tx::bytes " \
        "[%0], [%1, {%2, %3}], [%4];" \
        :: "r"((uint32_t)(dst)), "l"(map), "r"((int)(cx)), "r"((int)(cy)), "r"((uint32_t)(mbar)) : "memory")

// ============================================================================
// Preprocessing kernels
// ============================================================================
static constexpr int CH4 = 128 * (K_DIM / 4);        // 131072 float4 per x chunk
static constexpr int SLICE4 = CH4 / XCHUNK_BLOCKS;   // 8192 float4 per block

// x -> fp16, chunked with completion counters. grid = 64*XCHUNK_BLOCKS, block 256.
__global__ void convert_x_chunks_kernel(const float4* __restrict__ x4) {
    const int chunk = blockIdx.x / XCHUNK_BLOCKS;
    const int slice = blockIdx.x % XCHUNK_BLOCKS;
    const size_t base = (size_t)chunk * CH4 + (size_t)slice * SLICE4;
    uint2* dst = reinterpret_cast<uint2*>(g_xh);
    const int tid = threadIdx.x;
#pragma unroll 4
    for (int i = tid; i < SLICE4; i += 256) {
        float4 v = x4[base + i];
        __half2 h0 = __floats2half2_rn(v.x, v.y);
        __half2 h1 = __floats2half2_rn(v.z, v.w);
        uint2 u;
        u.x = *reinterpret_cast<uint32_t*>(&h0);
        u.y = *reinterpret_cast<uint32_t*>(&h1);
        dst[base + i] = u;
    }
    __threadfence();
    __syncthreads();
    if (tid == 0) atomicAdd(&g_xdone[chunk], 1u);
}

// W'[o,k] = base[o,k] + SCALE * sum_r B[o,r]*A[r,k], fp16 output
__global__ void build_w_kernel(const float4* __restrict__ base, const float4* __restrict__ A,
                               const float* __restrict__ B, uint2* __restrict__ wh) {
    int idx = blockIdx.x * blockDim.x + threadIdx.x;   // over N_DIM * K_DIM/4
    if (idx >= N_DIM * (K_DIM / 4)) return;
    int o = idx / (K_DIM / 4);
    int kq = idx - o * (K_DIM / 4);
    float4 acc = base[idx];
#pragma unroll
    for (int r = 0; r < LORA_R; r++) {
        float b = SCALE_F * __ldg(&B[o * LORA_R + r]);
        float4 a = __ldg(&A[r * (K_DIM / 4) + kq]);
        acc.x = fmaf(b, a.x, acc.x);
        acc.y = fmaf(b, a.y, acc.y);
        acc.z = fmaf(b, a.z, acc.z);
        acc.w = fmaf(b, a.w, acc.w);
    }
    __half2 h0 = __floats2half2_rn(acc.x, acc.y);
    __half2 h1 = __floats2half2_rn(acc.z, acc.w);
    uint2 u;
    u.x = *reinterpret_cast<uint32_t*>(&h0);
    u.y = *reinterpret_cast<uint32_t*>(&h1);
    wh[idx] = u;
}

// ============================================================================
// Persistent GEMM kernel: out = xh @ wh^T + bias, x chunks gated by counters
// ============================================================================
static constexpr int A_HALF    = 128 * BK * 2;            // 16384
static constexpr int A_BYTES   = 2 * A_HALF;              // 32768
static constexpr int B_BYTES   = TN * BK * 2;             // 16384
static constexpr int STG_BYTES = A_BYTES + B_BYTES;       // 49152
static constexpr int SMEM_TMEMPTR = 0;
static constexpr int BAR_FULL  = 16;
static constexpr int BAR_EMPTY = 48;
static constexpr int BAR_DONE  = 80;
static constexpr int BAR_EPI   = 96;
static constexpr int SMEM_TILES = 1024;
static constexpr int GEMM_SMEM = SMEM_TILES + STAGES * STG_BYTES;  // 197632

static constexpr uint32_t GEMM_IDESC_N128 =
    (1u << 4) | ((128 / 8) << 17) | ((128 / 16) << 24);

// ---- fallback constants ----
static constexpr int FB_ROWB   = 144;
static constexpr int FB_A_TILE = 256 * FB_ROWB;
static constexpr int FB_B_TILE = 128 * FB_ROWB;
static constexpr int FB_STAGE  = FB_A_TILE + FB_B_TILE;

#if !defined(__CUDA_ARCH__) || !defined(__CUDA_ARCH_FEAT_SM103_ALL)
__device__ __forceinline__ void cp_async16(uint32_t dst, const void* src) {
    asm volatile("cp.async.cg.shared.global [%0], [%1], 16;" :: "r"(dst), "l"(src) : "memory");
}
__device__ __forceinline__ void ldsm_x4(uint32_t* r, uint32_t addr) {
    asm volatile("ldmatrix.sync.aligned.m8n8.x4.shared.b16 {%0,%1,%2,%3}, [%4];"
                 : "=r"(r[0]), "=r"(r[1]), "=r"(r[2]), "=r"(r[3]) : "r"(addr));
}
__device__ __forceinline__ void mma16816(float* c, const uint32_t* a, uint32_t b0, uint32_t b1) {
    asm volatile("mma.sync.aligned.m16n8k16.row.col.f32.f16.f16.f32 "
                 "{%0,%1,%2,%3}, {%4,%5,%6,%7}, {%8,%9}, {%0,%1,%2,%3};"
                 : "+f"(c[0]), "+f"(c[1]), "+f"(c[2]), "+f"(c[3])
                 : "r"(a[0]), "r"(a[1]), "r"(a[2]), "r"(a[3]), "r"(b0), "r"(b1));
}
#endif

__global__ void __launch_bounds__(256, 1) lora_gemm_kernel(
    const __grid_constant__ CUtensorMap tmap_a,
    const __grid_constant__ CUtensorMap tmap_b,
    const __half* __restrict__ xh,
    const __half* __restrict__ wh,
    const float* __restrict__ bias,
    float* __restrict__ out)
{
    extern __shared__ __align__(1024) char smem[];
    __shared__ unsigned s_epoch;
    const uint32_t sb = smem_u32(smem);
    const int tid = threadIdx.x;
    const int wid = tid >> 5;
    const int lane = tid & 31;

    if (tid == 0) s_epoch = atomicAdd(&g_cta_epoch[blockIdx.x], 1u);

#if defined(__CUDA_ARCH_FEAT_SM103_ALL)
    // =========== persistent tcgen05 ping-pong, x-chunk gated ================
    if (wid == 4) {
        TCGEN05_ALLOC(sb + SMEM_TMEMPTR, 512);
        TCGEN05_RELINQUISH();
    }
    if (tid == 0) {
#pragma unroll
        for (int s = 0; s < STAGES; s++) {
            MBARRIER_INIT(sb + BAR_FULL + 8 * s, 1);
            MBARRIER_INIT(sb + BAR_EMPTY + 8 * s, 1);
        }
#pragma unroll
        for (int b = 0; b < 2; b++) {
            MBARRIER_INIT(sb + BAR_DONE + 8 * b, 1);
            MBARRIER_INIT(sb + BAR_EPI + 8 * b, 1);
        }
    }
    __syncthreads();
    TCGEN05_FENCE_AFTER();

    const unsigned xthresh = (unsigned)XCHUNK_BLOCKS * (s_epoch + 1u);

    uint32_t tmem;
    asm volatile("ld.shared.b32 %0, [%1];" : "=r"(tmem) : "r"(sb + SMEM_TMEMPTR));

    if (wid == 5) {
        // ---- TMA producer warp (gated on x chunk counters) ----
        uint32_t elected;
        asm volatile("{\n\t.reg .pred P;\n\telect.sync _|P, 0xFFFFFFFF;\n\tselp.b32 %0, 1, 0, P;\n\t}"
                     : "=r"(elected));
        int s = 0, ph = 1;
        for (int t = blockIdx.x; t < NTILES; t += gridDim.x) {
            const int m0 = (t / NT_CNT) * TM;
            const int n0 = (t % NT_CNT) * TN;
            const int cm = m0 >> 7;
            wait_cnt(&g_xdone[cm], xthresh);
            wait_cnt(&g_xdone[cm + 1], xthresh);
            asm volatile("fence.proxy.async;" ::: "memory");
            for (int kt = 0; kt < KTILES; kt++) {
                MBARRIER_WAIT_PARITY(sb + BAR_EMPTY + 8 * s, ph);
                if (elected) {
                    uint32_t full = sb + BAR_FULL + 8 * s;
                    MBARRIER_EXPECT_TX(full, STG_BYTES);
                    uint32_t dst = sb + SMEM_TILES + s * STG_BYTES;
                    TMA_LOAD_2D(dst,           &tmap_a, kt * BK, m0,       full);
                    TMA_LOAD_2D(dst + A_HALF,  &tmap_a, kt * BK, m0 + 128, full);
                    TMA_LOAD_2D(dst + A_BYTES, &tmap_b, kt * BK, n0,       full);
                }
                if (++s == STAGES) { s = 0; ph ^= 1; }
            }
        }
    } else if (wid == 4) {
        // ---- MMA warp ----
        uint32_t elected;
        asm volatile("{\n\t.reg .pred P;\n\telect.sync _|P, 0xFFFFFFFF;\n\tselp.b32 %0, 1, 0, P;\n\t}"
                     : "=r"(elected));
        int s = 0, ph = 0;
        int i = 0;
        for (int t = blockIdx.x; t < NTILES; t += gridDim.x, i++) {
            const int b = i & 1;
            const uint32_t dbase = tmem + b * 256;
            if (i >= 2) {
                MBARRIER_WAIT_PARITY(sb + BAR_EPI + 8 * b, ((i >> 1) ^ 1) & 1);
            }
            for (int kt = 0; kt < KTILES; kt++) {
                MBARRIER_WAIT_PARITY(sb + BAR_FULL + 8 * s, ph);
                if (elected) {
                    uint32_t stg = sb + SMEM_TILES + s * STG_BYTES;
                    uint64_t ad0 = MAKE_SMEM_DESC(stg);
                    uint64_t ad1 = MAKE_SMEM_DESC(stg + A_HALF);
                    uint64_t bd  = MAKE_SMEM_DESC(stg + A_BYTES);
                    uint32_t en0 = (kt == 0) ? 0u : 1u;
#pragma unroll
                    for (int j = 0; j < BK / 16; j++) {
                        uint32_t en = (j == 0) ? en0 : 1u;
                        uint32_t zero = 0u;
#define MMA_ONE(doff, adesc) \
                        asm volatile( \
                            "{\n\t.reg .pred p;\n\tsetp.ne.u32 p, %5, 0;\n\t" \
                            "tcgen05.mma.cta_group::1.kind::f16 [%0], %1, %2, %3, {%4, %4, %4, %4}, p;\n\t}" \
                            :: "r"(dbase + (doff)), "l"(adesc), "l"(bd + j * 2), \
                               "r"(GEMM_IDESC_N128), "r"(zero), "r"(en) : "memory")
                        MMA_ONE(0,   ad0 + j * 2);
                        MMA_ONE(128, ad1 + j * 2);
#undef MMA_ONE
                    }
                    TCGEN05_COMMIT(sb + BAR_EMPTY + 8 * s);
                }
                if (++s == STAGES) { s = 0; ph ^= 1; }
            }
            if (elected) {
                TCGEN05_COMMIT(sb + BAR_DONE + 8 * b);
            }
        }
    } else if (wid < 4) {
        // ---- epilogue warpgroup (warps 0-3) ----
        int i = 0;
        for (int t = blockIdx.x; t < NTILES; t += gridDim.x, i++) {
            const int b = i & 1;
            const int m0 = (t / NT_CNT) * TM;
            const int n0 = (t % NT_CNT) * TN;
            const uint32_t dbase = tmem + b * 256;
            MBARRIER_WAIT_PARITY(sb + BAR_DONE + 8 * b, (i >> 1) & 1);
            TCGEN05_FENCE_AFTER();
#pragma unroll
            for (int mh = 0; mh < 2; mh++) {
                const int row_g = m0 + mh * 128 + wid * 32 + lane;
                float* orow = out + (size_t)row_g * N_DIM + n0;
#pragma unroll
                for (int cb = 0; cb < TN / 32; cb++) {
                    uint32_t r[32];
                    TCGEN05_LD_32X32B_X32(r, dbase + mh * 128 + cb * 32);
                    TCGEN05_WAIT_LD();
#pragma unroll
                    for (int c4 = 0; c4 < 8; c4++) {
                        int col = cb * 32 + c4 * 4;
                        float4 v;
                        v.x = __uint_as_float(r[c4 * 4 + 0]) + __ldg(&bias[n0 + col + 0]);
                        v.y = __uint_as_float(r[c4 * 4 + 1]) + __ldg(&bias[n0 + col + 1]);
                        v.z = __uint_as_float(r[c4 * 4 + 2]) + __ldg(&bias[n0 + col + 2]);
                        v.w = __uint_as_float(r[c4 * 4 + 3]) + __ldg(&bias[n0 + col + 3]);
                        *reinterpret_cast<float4*>(orow + col) = v;
                    }
                }
            }
            TCGEN05_FENCE_BEFORE();
            asm volatile("bar.sync 1, 128;" ::: "memory");
            if (tid == 0) {
                MBARRIER_ARRIVE(sb + BAR_EPI + 8 * b);
            }
        }
    }

    __syncthreads();
    if (wid == 4) {
        TCGEN05_DEALLOC(tmem, 512);
    }

#else
    // ======================= mma.sync fallback path ==========================
    (void)tmap_a; (void)tmap_b;
    __syncthreads();
    const unsigned xthresh = (unsigned)XCHUNK_BLOCKS * (s_epoch + 1u);
    if (tid == 0) {
        for (int c = 0; c < 64; c++) wait_cnt(&g_xdone[c], xthresh);
    }
    __syncthreads();

    const int wm = (wid >> 1) * 64;
    const int wn = (wid & 1) * 64;
    const int l = lane;
    const int a_r = (l & 7) + ((l >> 3) & 1) * 8;
    const int a_c = (l >> 4) * 8;
    const int b_r = (l & 7) + ((l >> 4) & 1) * 8;
    const int b_c = ((l >> 3) & 1) * 8;

    for (int t = blockIdx.x; t < NTILES; t += gridDim.x) {
        const int m0 = (t / NT_CNT) * TM;
        const int n0 = (t % NT_CNT) * TN;
        float acc[4][8][4];
#pragma unroll
        for (int mt = 0; mt < 4; mt++)
#pragma unroll
            for (int nt = 0; nt < 8; nt++)
#pragma unroll
                for (int q = 0; q < 4; q++) acc[mt][nt][q] = 0.0f;

        {
            const __half* ga = xh + (size_t)(m0 + tid) * K_DIM;
            uint32_t da = sb + tid * FB_ROWB;
#pragma unroll
            for (int q = 0; q < 8; q++) cp_async16(da + q * 16, ga + q * 8);
            int brow = tid >> 1, half = tid & 1;
            const __half* gb = wh + (size_t)(n0 + brow) * K_DIM + half * 32;
            uint32_t db = sb + FB_A_TILE + brow * FB_ROWB + half * 64;
#pragma unroll
            for (int q = 0; q < 4; q++) cp_async16(db + q * 16, gb + q * 8);
            asm volatile("cp.async.commit_group;" ::: "memory");
        }

        for (int kt = 0; kt < KTILES; kt++) {
            if (kt + 1 < KTILES) {
                int s = (kt + 1) & 1;
                const __half* ga = xh + (size_t)(m0 + tid) * K_DIM + (kt + 1) * BK;
                uint32_t da = sb + s * FB_STAGE + tid * FB_ROWB;
#pragma unroll
                for (int q = 0; q < 8; q++) cp_async16(da + q * 16, ga + q * 8);
                int brow = tid >> 1, half = tid & 1;
                const __half* gb = wh + (size_t)(n0 + brow) * K_DIM + (kt + 1) * BK + half * 32;
                uint32_t db = sb + s * FB_STAGE + FB_A_TILE + brow * FB_ROWB + half * 64;
#pragma unroll
                for (int q = 0; q < 4; q++) cp_async16(db + q * 16, gb + q * 8);
                asm volatile("cp.async.commit_group;" ::: "memory");
                asm volatile("cp.async.wait_group 1;" ::: "memory");
            } else {
                asm volatile("cp.async.wait_group 0;" ::: "memory");
            }
            __syncthreads();

            uint32_t sA = sb + (kt & 1) * FB_STAGE;
            uint32_t sB = sA + FB_A_TILE;
#pragma unroll
            for (int ks = 0; ks < BK / 16; ks++) {
                uint32_t afrag[4][4];
#pragma unroll
                for (int mt = 0; mt < 4; mt++) {
                    uint32_t addr = sA + (wm + mt * 16 + a_r) * FB_ROWB + (ks * 16 + a_c) * 2;
                    ldsm_x4(afrag[mt], addr);
                }
                uint32_t bfrag[4][4];
#pragma unroll
                for (int p = 0; p < 4; p++) {
                    uint32_t addr = sB + (wn + p * 16 + b_r) * FB_ROWB + (ks * 16 + b_c) * 2;
                    ldsm_x4(bfrag[p], addr);
                }
#pragma unroll
                for (int mt = 0; mt < 4; mt++)
#pragma unroll
                    for (int nt = 0; nt < 8; nt++)
                        mma16816(acc[mt][nt], afrag[mt],
                                 bfrag[nt >> 1][(nt & 1) * 2], bfrag[nt >> 1][(nt & 1) * 2 + 1]);
            }
            __syncthreads();
        }

#pragma unroll
        for (int mt = 0; mt < 4; mt++) {
#pragma unroll
            for (int nt = 0; nt < 8; nt++) {
                int r0 = m0 + wm + mt * 16 + (l >> 2);
                int c0 = n0 + wn + nt * 8 + (l & 3) * 2;
                float bx = __ldg(&bias[c0]);
                float by = __ldg(&bias[c0 + 1]);
                float2 v0 = make_float2(acc[mt][nt][0] + bx, acc[mt][nt][1] + by);
                float2 v1 = make_float2(acc[mt][nt][2] + bx, acc[mt][nt][3] + by);
                *reinterpret_cast<float2*>(&out[(size_t)r0 * N_DIM + c0]) = v0;
                *reinterpret_cast<float2*>(&out[(size_t)(r0 + 8) * N_DIM + c0]) = v1;
            }
        }
        __syncthreads();
    }
#endif
}

// ============================================================================
// Host launch
// ============================================================================
typedef CUresult (*tmap_encode_t)(CUtensorMap*, CUtensorMapDataType, cuuint32_t, void*,
                                  const cuuint64_t*, const cuuint64_t*, const cuuint32_t*,
                                  const cuuint32_t*, CUtensorMapInterleave, CUtensorMapSwizzle,
                                  CUtensorMapL2promotion, CUtensorMapFloatOOBfill);

extern "C" void kernel_launch(void* const* d_in, const int* in_sizes, int n_in,
                              void* d_out, int out_size) {
    (void)in_sizes; (void)n_in; (void)out_size;
    const float* x    = (const float*)d_in[0];
    const float* base = (const float*)d_in[1];
    const float* lA   = (const float*)d_in[2];
    const float* lB   = (const float*)d_in[3];
    const float* bias = (const float*)d_in[4];
    float* out = (float*)d_out;

    void* xh_p = nullptr;
    void* wh_p = nullptr;
    cudaGetSymbolAddress(&xh_p, g_xh);
    cudaGetSymbolAddress(&wh_p, g_wh);

    static tmap_encode_t encode = nullptr;
    if (!encode) {
        void* pfn = nullptr;
        cudaDriverEntryPointQueryResult qres;
#if CUDART_VERSION >= 12050
        cudaGetDriverEntryPointByVersion("cuTensorMapEncodeTiled", &pfn, 12000,
                                         cudaEnableDefault, &qres);
#else
        cudaGetDriverEntryPoint("cuTensorMapEncodeTiled", &pfn, cudaEnableDefault, &qres);
#endif
        encode = (tmap_encode_t)pfn;
    }

    CUtensorMap mapA{}, mapB{};
    if (encode) {
        {
            cuuint64_t dims[2]    = {K_DIM, M_DIM};
            cuuint64_t strides[1] = {K_DIM * sizeof(__half)};
            cuuint32_t box[2]     = {BK, 128};
            cuuint32_t es[2]      = {1, 1};
            encode(&mapA, CU_TENSOR_MAP_DATA_TYPE_FLOAT16, 2, xh_p, dims, strides, box, es,
                   CU_TENSOR_MAP_INTERLEAVE_NONE, CU_TENSOR_MAP_SWIZZLE_128B,
                   CU_TENSOR_MAP_L2_PROMOTION_L2_128B, CU_TENSOR_MAP_FLOAT_OOB_FILL_NONE);
        }
        {
            cuuint64_t dims[2]    = {K_DIM, N_DIM};
            cuuint64_t strides[1] = {K_DIM * sizeof(__half)};
            cuuint32_t box[2]     = {BK, TN};
            cuuint32_t es[2]      = {1, 1};
            encode(&mapB, CU_TENSOR_MAP_DATA_TYPE_FLOAT16, 2, wh_p, dims, strides, box, es,
                   CU_TENSOR_MAP_INTERLEAVE_NONE, CU_TENSOR_MAP_SWIZZLE_128B,
                   CU_TENSOR_MAP_L2_PROMOTION_L2_128B, CU_TENSOR_MAP_FLOAT_OOB_FILL_NONE);
        }
    }

    int dev = 0, smcount = 148;
    cudaGetDevice(&dev);
    cudaDeviceGetAttribute(&smcount, cudaDevAttrMultiProcessorCount, dev);
    if (smcount < 1) smcount = 148;
    if (smcount > 1024) smcount = 1024;

    cudaFuncSetAttribute(lora_gemm_kernel, cudaFuncAttributeMaxDynamicSharedMemorySize,
                         GEMM_SMEM);

    // ---- forked-stream overlap: convert_x runs concurrently with the GEMM ----
    static cudaStream_t s2 = nullptr;
    static cudaEvent_t evFork = nullptr, evJoin = nullptr;
    static bool tried = false;
    if (!tried) {
        tried = true;
        if (cudaStreamCreateWithFlags(&s2, cudaStreamNonBlocking) != cudaSuccess) s2 = nullptr;
        if (cudaEventCreateWithFlags(&evFork, cudaEventDisableTiming) != cudaSuccess) evFork = nullptr;
        if (cudaEventCreateWithFlags(&evJoin, cudaEventDisableTiming) != cudaSuccess) evJoin = nullptr;
    }

    bool forked = false;
    if (s2 && evFork && evJoin) {
        if (cudaEventRecord(evFork, 0) == cudaSuccess &&
            cudaStreamWaitEvent(s2, evFork, 0) == cudaSuccess) {
            convert_x_chunks_kernel<<<64 * XCHUNK_BLOCKS, 256, 0, s2>>>((const float4*)x);
            if (cudaEventRecord(evJoin, s2) == cudaSuccess) {
                forked = true;
            }
        }
    }
    if (!forked) {
        // serial fallback on the main stream
        convert_x_chunks_kernel<<<64 * XCHUNK_BLOCKS, 256>>>((const float4*)x);
    }

    // W' build on the main stream (all W chunks needed at GEMM start)
    {
        int n4 = N_DIM * (K_DIM / 4);
        build_w_kernel<<<(n4 + 255) / 256, 256>>>((const float4*)base, (const float4*)lA,
                                                  lB, (uint2*)wh_p);
    }

    lora_gemm_kernel<<<smcount, 256, GEMM_SMEM>>>(
        mapA, mapB, (const __half*)xh_p, (const __half*)wh_p, bias, out);

    if (forked) {
        cudaStreamWaitEvent(0, evJoin, 0);
    }
}